// round 9
// baseline (speedup 1.0000x reference)
#include <cuda_runtime.h>

#define NN 100000
#define EMAX 1600000

// ---------------- scratch (device globals; kernels reference them directly) -
__device__ __align__(256) int   g_deg[NN];
__device__ __align__(256) int   g_cnt[NN];
__device__ __align__(256) int   g_rowstart[NN + 1];
__device__ __align__(256) int   g_edge_src[EMAX];
__device__ __align__(256) float g_agg[(size_t)NN * 128];
__device__ __align__(256) float g_h[(size_t)NN * 128];

// ---------------- init ------------------------------------------------------
__global__ void zero_kernel() {
    int i = blockIdx.x * blockDim.x + threadIdx.x;
    if (i < NN) { g_deg[i] = 0; g_cnt[i] = 0; }
}

// ---------------- degree count (edge_index delivered as int32) --------------
__global__ void degree_kernel(const int* __restrict__ edge, int E) {
    int e = blockIdx.x * blockDim.x + threadIdx.x;
    if (e < E) {
        int dst = edge[(size_t)E + e];
        atomicAdd(&g_deg[dst], 1);
    }
}

// ---------------- exclusive scan of degrees (single block) ------------------
__global__ void scan_kernel() {
    __shared__ int warp_sums[32];
    __shared__ int s_carry;
    int tid = threadIdx.x, lane = tid & 31, wid = tid >> 5;
    if (tid == 0) s_carry = 0;
    __syncthreads();
    for (int base = 0; base < NN; base += 1024) {
        int i = base + tid;
        int v = (i < NN) ? g_deg[i] : 0;
        int x = v;
        #pragma unroll
        for (int off = 1; off < 32; off *= 2) {
            int t = __shfl_up_sync(0xffffffffu, x, off);
            if (lane >= off) x += t;
        }
        if (lane == 31) warp_sums[wid] = x;
        __syncthreads();
        if (wid == 0) {
            int w = warp_sums[lane];
            #pragma unroll
            for (int off = 1; off < 32; off *= 2) {
                int t = __shfl_up_sync(0xffffffffu, w, off);
                if (lane >= off) w += t;
            }
            warp_sums[lane] = w;
        }
        __syncthreads();
        int warp_off = (wid > 0) ? warp_sums[wid - 1] : 0;
        int incl = x + warp_off;
        int carry = s_carry;
        if (i < NN) g_rowstart[i] = carry + incl - v;
        __syncthreads();
        if (tid == 1023) s_carry = carry + incl;
        __syncthreads();
    }
    if (tid == 0) g_rowstart[NN] = s_carry;
}

// ---------------- scatter edges into CSR slots ------------------------------
__global__ void scatter_kernel(const int* __restrict__ edge, int E) {
    int e = blockIdx.x * blockDim.x + threadIdx.x;
    if (e < E) {
        int src = edge[e];
        int dst = edge[(size_t)E + e];
        int pos = g_rowstart[dst] + atomicAdd(&g_cnt[dst], 1);
        g_edge_src[pos] = src;
    }
}

// ---------------- pull-style mean aggregation (warp per node) ---------------
// FEAT_FROM_H: read features from g_h (layer 2) instead of the x param.
// Output always goes to g_agg.
template <int D, bool FEAT_FROM_H>
__global__ void agg_kernel(const float* __restrict__ xparam) {
    const float* feat = FEAT_FROM_H ? (const float*)g_h : xparam;
    int warp = (blockIdx.x * blockDim.x + threadIdx.x) >> 5;
    int lane = threadIdx.x & 31;
    if (warp >= NN) return;
    int s = g_rowstart[warp];
    int e = g_rowstart[warp + 1];
    constexpr int NF = D / 64;  // float2 per lane per group
    float2 acc[NF];
    #pragma unroll
    for (int f = 0; f < NF; f++) acc[f] = make_float2(0.f, 0.f);
    for (int i = s; i < e; i++) {
        int src = __ldg(&g_edge_src[i]);
        const float2* row = (const float2*)(feat + (size_t)src * D);
        #pragma unroll
        for (int f = 0; f < NF; f++) {
            float2 v = __ldg(&row[lane + f * 32]);
            acc[f].x += v.x; acc[f].y += v.y;
        }
    }
    int deg = e - s;
    float inv = 1.0f / (float)(deg > 1 ? deg : 1);
    float2* o = (float2*)(g_agg + (size_t)warp * D);
    #pragma unroll
    for (int f = 0; f < NF; f++)
        o[lane + f * 32] = make_float2(acc[f].x * inv, acc[f].y * inv);
}

// ---------------- fused GEMM: out = [agg|x] @ [W_l|W_r]^T + b (opt relu) ----
// A (first K cols)  = g_agg (always).
// A (second K cols) = g_h if X_FROM_H else the xparam pointer.
// Output           = g_h if OUT_TO_H else the out param.
// Tile: 64 rows x 128 cols, 256 threads, 4x8 accumulators per thread.
template <int K, bool RELU, bool X_FROM_H, bool OUT_TO_H>
__global__ __launch_bounds__(256) void gemm_kernel(
    const float* __restrict__ xparam,
    const float* __restrict__ Wl, const float* __restrict__ Wr,
    const float* __restrict__ bias, float* __restrict__ outparam)
{
    constexpr int KT = 16;
    __shared__ float As[KT][68];    // [k][row], padded
    __shared__ float Bs[KT][132];   // [k][col], padded

    const float* xmat = X_FROM_H ? (const float*)g_h : xparam;
    float* out = OUT_TO_H ? (float*)g_h : outparam;

    int tid = threadIdx.x;
    int tx = tid & 15;          // col group: cols tx*8 .. tx*8+7
    int ty = tid >> 4;          // row group: rows ty*4 .. ty*4+3
    int rowbase = blockIdx.x * 64;

    float acc[4][8];
    #pragma unroll
    for (int r = 0; r < 4; r++)
        #pragma unroll
        for (int c = 0; c < 8; c++) acc[r][c] = 0.f;

    // A-load mapping: 64 rows x 16 k -> 1 float4 per thread
    int a_row = tid >> 2;
    int a_kk  = (tid & 3) * 4;
    // B-load mapping: 128 cols x 16 k -> 2 float4 per thread
    int b_o   = tid >> 1;
    int b_kk  = (tid & 1) * 8;

    for (int kc = 0; kc < 2 * K; kc += KT) {
        bool first = (kc < K);
        const float* amat = first ? (const float*)g_agg : xmat;
        const float* wmat = first ? Wl : Wr;
        int kbase = first ? kc : kc - K;

        // load A tile
        {
            int grow = rowbase + a_row;
            float4 v = make_float4(0.f, 0.f, 0.f, 0.f);
            if (grow < NN)
                v = *(const float4*)(amat + (size_t)grow * K + kbase + a_kk);
            As[a_kk + 0][a_row] = v.x;
            As[a_kk + 1][a_row] = v.y;
            As[a_kk + 2][a_row] = v.z;
            As[a_kk + 3][a_row] = v.w;
        }
        // load B tile (W is [128][K] row-major)
        {
            const float* wp = wmat + (size_t)b_o * K + kbase + b_kk;
            float4 v0 = *(const float4*)(wp);
            float4 v1 = *(const float4*)(wp + 4);
            Bs[b_kk + 0][b_o] = v0.x;
            Bs[b_kk + 1][b_o] = v0.y;
            Bs[b_kk + 2][b_o] = v0.z;
            Bs[b_kk + 3][b_o] = v0.w;
            Bs[b_kk + 4][b_o] = v1.x;
            Bs[b_kk + 5][b_o] = v1.y;
            Bs[b_kk + 6][b_o] = v1.z;
            Bs[b_kk + 7][b_o] = v1.w;
        }
        __syncthreads();

        #pragma unroll
        for (int k = 0; k < KT; k++) {
            float4 a4 = *(const float4*)&As[k][ty * 4];
            float4 b0 = *(const float4*)&Bs[k][tx * 8];
            float4 b1 = *(const float4*)&Bs[k][tx * 8 + 4];
            float a[4] = {a4.x, a4.y, a4.z, a4.w};
            float b[8] = {b0.x, b0.y, b0.z, b0.w, b1.x, b1.y, b1.z, b1.w};
            #pragma unroll
            for (int r = 0; r < 4; r++)
                #pragma unroll
                for (int c = 0; c < 8; c++)
                    acc[r][c] += a[r] * b[c];
        }
        __syncthreads();
    }

    // epilogue
    float bv[8];
    #pragma unroll
    for (int c = 0; c < 8; c++) bv[c] = bias[tx * 8 + c];
    #pragma unroll
    for (int r = 0; r < 4; r++) {
        int grow = rowbase + ty * 4 + r;
        if (grow < NN) {
            float* op = out + (size_t)grow * 128 + tx * 8;
            #pragma unroll
            for (int c = 0; c < 8; c++) {
                float v = acc[r][c] + bv[c];
                if (RELU) v = v > 0.f ? v : 0.f;
                op[c] = v;
            }
        }
    }
}

// ---------------- launch ----------------------------------------------------
extern "C" void kernel_launch(void* const* d_in, const int* in_sizes, int n_in,
                              void* d_out, int out_size) {
    const float* x    = (const float*)d_in[0];
    const int*   edge = (const int*)d_in[1];     // int64 in reference, delivered as int32
    const float* W1l  = (const float*)d_in[2];
    const float* W1r  = (const float*)d_in[3];
    const float* b1   = (const float*)d_in[4];
    const float* W2l  = (const float*)d_in[5];
    const float* W2r  = (const float*)d_in[6];
    const float* b2   = (const float*)d_in[7];
    float* out = (float*)d_out;

    int E = in_sizes[1] / 2;

    // build CSR (by destination)
    zero_kernel<<<(NN + 255) / 256, 256>>>();
    degree_kernel<<<(E + 255) / 256, 256>>>(edge, E);
    scan_kernel<<<1, 1024>>>();
    scatter_kernel<<<(E + 255) / 256, 256>>>(edge, E);

    // layer 1: agg(x) -> g_agg ; [g_agg|x] @ [W1l|W1r]^T + b1, relu -> g_h
    agg_kernel<64, false><<<(NN * 32 + 255) / 256, 256>>>(x);
    gemm_kernel<64, true, false, true><<<(NN + 63) / 64, 256>>>(x, W1l, W1r, b1, nullptr);

    // layer 2: agg(g_h) -> g_agg ; [g_agg|g_h] @ [W2l|W2r]^T + b2 -> out
    agg_kernel<128, true><<<(NN * 32 + 255) / 256, 256>>>(nullptr);
    gemm_kernel<128, false, true, false><<<(NN + 63) / 64, 256>>>(nullptr, W2l, W2r, b2, out);
}

// round 13
// speedup vs baseline: 1.9221x; 1.9221x over previous
#include <cuda_runtime.h>
#include <cstdint>

#define NN 100000
#define EMAX 1600000

// ---------------- scratch (device globals; kernels reference them directly) -
__device__ __align__(256) int   g_deg[NN];
__device__ __align__(256) int   g_cnt[NN];
__device__ __align__(256) int   g_rowstart[NN + 1];
__device__ __align__(256) int   g_edge_src[EMAX];
__device__ __align__(256) float g_agg[(size_t)NN * 128];
__device__ __align__(256) float g_h[(size_t)NN * 128];

// ---------------- init ------------------------------------------------------
__global__ void zero_kernel() {
    int i = blockIdx.x * blockDim.x + threadIdx.x;
    if (i < NN) { g_deg[i] = 0; g_cnt[i] = 0; }
}

// ---------------- degree count (edge_index delivered as int32) --------------
__global__ void degree_kernel(const int* __restrict__ edge, int E) {
    int e = blockIdx.x * blockDim.x + threadIdx.x;
    if (e < E) {
        int dst = edge[(size_t)E + e];
        atomicAdd(&g_deg[dst], 1);
    }
}

// ---------------- exclusive scan of degrees (single block) ------------------
__global__ void scan_kernel() {
    __shared__ int warp_sums[32];
    __shared__ int s_carry;
    int tid = threadIdx.x, lane = tid & 31, wid = tid >> 5;
    if (tid == 0) s_carry = 0;
    __syncthreads();
    for (int base = 0; base < NN; base += 1024) {
        int i = base + tid;
        int v = (i < NN) ? g_deg[i] : 0;
        int x = v;
        #pragma unroll
        for (int off = 1; off < 32; off *= 2) {
            int t = __shfl_up_sync(0xffffffffu, x, off);
            if (lane >= off) x += t;
        }
        if (lane == 31) warp_sums[wid] = x;
        __syncthreads();
        if (wid == 0) {
            int w = warp_sums[lane];
            #pragma unroll
            for (int off = 1; off < 32; off *= 2) {
                int t = __shfl_up_sync(0xffffffffu, w, off);
                if (lane >= off) w += t;
            }
            warp_sums[lane] = w;
        }
        __syncthreads();
        int warp_off = (wid > 0) ? warp_sums[wid - 1] : 0;
        int incl = x + warp_off;
        int carry = s_carry;
        if (i < NN) g_rowstart[i] = carry + incl - v;
        __syncthreads();
        if (tid == 1023) s_carry = carry + incl;
        __syncthreads();
    }
    if (tid == 0) g_rowstart[NN] = s_carry;
}

// ---------------- scatter edges into CSR slots ------------------------------
__global__ void scatter_kernel(const int* __restrict__ edge, int E) {
    int e = blockIdx.x * blockDim.x + threadIdx.x;
    if (e < E) {
        int src = edge[e];
        int dst = edge[(size_t)E + e];
        int pos = g_rowstart[dst] + atomicAdd(&g_cnt[dst], 1);
        g_edge_src[pos] = src;
    }
}

// ---------------- pull-style mean aggregation (warp per node) ---------------
template <int D, bool FEAT_FROM_H>
__global__ void agg_kernel(const float* __restrict__ xparam) {
    const float* feat = FEAT_FROM_H ? (const float*)g_h : xparam;
    int warp = (blockIdx.x * blockDim.x + threadIdx.x) >> 5;
    int lane = threadIdx.x & 31;
    if (warp >= NN) return;
    int s = g_rowstart[warp];
    int e = g_rowstart[warp + 1];
    constexpr int NF = D / 64;  // float2 per lane per group
    float2 acc[NF];
    #pragma unroll
    for (int f = 0; f < NF; f++) acc[f] = make_float2(0.f, 0.f);
    for (int i = s; i < e; i++) {
        int src = __ldg(&g_edge_src[i]);
        const float2* row = (const float2*)(feat + (size_t)src * D);
        #pragma unroll
        for (int f = 0; f < NF; f++) {
            float2 v = __ldg(&row[lane + f * 32]);
            acc[f].x += v.x; acc[f].y += v.y;
        }
    }
    int deg = e - s;
    float inv = 1.0f / (float)(deg > 1 ? deg : 1);
    float2* o = (float2*)(g_agg + (size_t)warp * D);
    #pragma unroll
    for (int f = 0; f < NF; f++)
        o[lane + f * 32] = make_float2(acc[f].x * inv, acc[f].y * inv);
}

// ---------------- TF32 helpers ----------------------------------------------
__device__ __forceinline__ uint32_t f32_to_tf32(float f) {
    uint32_t r;
    asm("cvt.rna.tf32.f32 %0, %1;" : "=r"(r) : "f"(f));
    return r;
}

__device__ __forceinline__ void mma_tf32(
    float& c0, float& c1, float& c2, float& c3,
    uint32_t a0, uint32_t a1, uint32_t a2, uint32_t a3,
    uint32_t b0, uint32_t b1)
{
    asm volatile(
        "mma.sync.aligned.m16n8k8.row.col.f32.tf32.tf32.f32 "
        "{%0,%1,%2,%3}, {%4,%5,%6,%7}, {%8,%9}, {%0,%1,%2,%3};"
        : "+f"(c0), "+f"(c1), "+f"(c2), "+f"(c3)
        : "r"(a0), "r"(a1), "r"(a2), "r"(a3), "r"(b0), "r"(b1));
}

// ---------------- tensor-core GEMM: out = [agg|xmat] @ [Wl|Wr]^T + b --------
// Block: 128 rows x 128 cols, 256 threads = 8 warps (4 along M x 2 along N).
// Warp tile: 32 (M) x 64 (N) via 2x8 grid of m16n8k8 TF32 mma.
// K-chunks of 32 staged in smem ([row][k], stride 36 -> conflict-free frags).
template <int K, bool RELU, bool X_FROM_H, bool OUT_TO_H>
__global__ __launch_bounds__(256) void gemm_tc_kernel(
    const float* __restrict__ xparam,
    const float* __restrict__ Wl, const float* __restrict__ Wr,
    const float* __restrict__ bias, float* __restrict__ outparam)
{
    constexpr int KT = 32;
    __shared__ uint32_t As[128][36];
    __shared__ uint32_t Bs[128][36];

    const float* xmat = X_FROM_H ? (const float*)g_h : xparam;
    float* out = OUT_TO_H ? (float*)g_h : outparam;

    int tid  = threadIdx.x;
    int lane = tid & 31;
    int wid  = tid >> 5;
    int warp_m = wid & 3;   // 0..3 -> M offset warp_m*32
    int warp_n = wid >> 2;  // 0..1 -> N offset warp_n*64
    int rowbase = blockIdx.x * 128;

    int qrow = lane >> 2;   // 0..7
    int qcol = lane & 3;    // 0..3

    float acc[2][8][4];
    #pragma unroll
    for (int m = 0; m < 2; m++)
        #pragma unroll
        for (int n = 0; n < 8; n++)
            #pragma unroll
            for (int r = 0; r < 4; r++) acc[m][n][r] = 0.f;

    // staging mapping: thread t loads row (t>>1), k-segment ((t&1)*16), 16 floats
    int st_row = tid >> 1;
    int st_kk  = (tid & 1) * 16;

    for (int kc = 0; kc < 2 * K; kc += KT) {
        bool first = (kc < K);
        const float* amat = first ? (const float*)g_agg : xmat;
        const float* wmat = first ? Wl : Wr;
        int kbase = first ? kc : kc - K;

        // A tile: 128 rows x 32 k
        {
            int grow = rowbase + st_row;
            const float* ap = amat + (size_t)grow * K + kbase + st_kk;
            #pragma unroll
            for (int v = 0; v < 4; v++) {
                float4 f = (grow < NN) ? *(const float4*)(ap + v * 4)
                                       : make_float4(0.f, 0.f, 0.f, 0.f);
                As[st_row][st_kk + v * 4 + 0] = f32_to_tf32(f.x);
                As[st_row][st_kk + v * 4 + 1] = f32_to_tf32(f.y);
                As[st_row][st_kk + v * 4 + 2] = f32_to_tf32(f.z);
                As[st_row][st_kk + v * 4 + 3] = f32_to_tf32(f.w);
            }
        }
        // B tile: Bs[n][k] = W[n][kbase+k], 128 n x 32 k
        {
            const float* wp = wmat + (size_t)st_row * K + kbase + st_kk;
            #pragma unroll
            for (int v = 0; v < 4; v++) {
                float4 f = *(const float4*)(wp + v * 4);
                Bs[st_row][st_kk + v * 4 + 0] = f32_to_tf32(f.x);
                Bs[st_row][st_kk + v * 4 + 1] = f32_to_tf32(f.y);
                Bs[st_row][st_kk + v * 4 + 2] = f32_to_tf32(f.z);
                Bs[st_row][st_kk + v * 4 + 3] = f32_to_tf32(f.w);
            }
        }
        __syncthreads();

        #pragma unroll
        for (int ks = 0; ks < KT; ks += 8) {
            // A fragments for 2 m-tiles
            uint32_t a[2][4];
            #pragma unroll
            for (int m = 0; m < 2; m++) {
                int r0 = warp_m * 32 + m * 16 + qrow;
                a[m][0] = As[r0][ks + qcol];
                a[m][1] = As[r0 + 8][ks + qcol];
                a[m][2] = As[r0][ks + 4 + qcol];
                a[m][3] = As[r0 + 8][ks + 4 + qcol];
            }
            #pragma unroll
            for (int n = 0; n < 8; n++) {
                int n0 = warp_n * 64 + n * 8 + qrow;
                uint32_t b0 = Bs[n0][ks + qcol];
                uint32_t b1 = Bs[n0][ks + 4 + qcol];
                #pragma unroll
                for (int m = 0; m < 2; m++)
                    mma_tf32(acc[m][n][0], acc[m][n][1], acc[m][n][2], acc[m][n][3],
                             a[m][0], a[m][1], a[m][2], a[m][3], b0, b1);
            }
        }
        __syncthreads();
    }

    // epilogue: c0/c1 -> (row, 2c..2c+1), c2/c3 -> (row+8, 2c..2c+1)
    #pragma unroll
    for (int n = 0; n < 8; n++) {
        int cbase = warp_n * 64 + n * 8 + 2 * qcol;
        float bv0 = bias[cbase];
        float bv1 = bias[cbase + 1];
        #pragma unroll
        for (int m = 0; m < 2; m++) {
            int r0 = rowbase + warp_m * 32 + m * 16 + qrow;
            float v0 = acc[m][n][0] + bv0;
            float v1 = acc[m][n][1] + bv1;
            float v2 = acc[m][n][2] + bv0;
            float v3 = acc[m][n][3] + bv1;
            if (RELU) {
                v0 = v0 > 0.f ? v0 : 0.f;
                v1 = v1 > 0.f ? v1 : 0.f;
                v2 = v2 > 0.f ? v2 : 0.f;
                v3 = v3 > 0.f ? v3 : 0.f;
            }
            if (r0 < NN)
                *(float2*)(out + (size_t)r0 * 128 + cbase) = make_float2(v0, v1);
            if (r0 + 8 < NN)
                *(float2*)(out + (size_t)(r0 + 8) * 128 + cbase) = make_float2(v2, v3);
        }
    }
}

// ---------------- launch ----------------------------------------------------
extern "C" void kernel_launch(void* const* d_in, const int* in_sizes, int n_in,
                              void* d_out, int out_size) {
    const float* x    = (const float*)d_in[0];
    const int*   edge = (const int*)d_in[1];     // int64 in reference, delivered as int32
    const float* W1l  = (const float*)d_in[2];
    const float* W1r  = (const float*)d_in[3];
    const float* b1   = (const float*)d_in[4];
    const float* W2l  = (const float*)d_in[5];
    const float* W2r  = (const float*)d_in[6];
    const float* b2   = (const float*)d_in[7];
    float* out = (float*)d_out;

    int E = in_sizes[1] / 2;

    // build CSR (by destination)
    zero_kernel<<<(NN + 255) / 256, 256>>>();
    degree_kernel<<<(E + 255) / 256, 256>>>(edge, E);
    scan_kernel<<<1, 1024>>>();
    scatter_kernel<<<(E + 255) / 256, 256>>>(edge, E);

    // layer 1: agg(x) -> g_agg ; [g_agg|x] @ [W1l|W1r]^T + b1, relu -> g_h
    agg_kernel<64, false><<<(NN * 32 + 255) / 256, 256>>>(x);
    gemm_tc_kernel<64, true, false, true><<<(NN + 127) / 128, 256>>>(x, W1l, W1r, b1, nullptr);

    // layer 2: agg(g_h) -> g_agg ; [g_agg|g_h] @ [W2l|W2r]^T + b2 -> out
    agg_kernel<128, true><<<(NN * 32 + 255) / 256, 256>>>(nullptr);
    gemm_tc_kernel<128, false, true, false><<<(NN + 127) / 128, 256>>>(nullptr, W2l, W2r, b2, out);
}